// round 12
// baseline (speedup 1.0000x reference)
#include <cuda_runtime.h>

// Gegenbauer (alpha=0.5 -> Legendre) embedding: out[row, i-1] = C_i(x[row]), i=1..64.
// Round 12: double-buffered smem staging removes the mid-pipeline barrier —
// pass-1 STS (buffer 1) no longer waits for pass-0 copy-out reads (buffer 0).
// 2 barriers total instead of 3; store injection stays continuous across the
// pass boundary. Otherwise the converged write-wall form: padded smem
// (PAD=9 f4, conflict-free STS/LDS), register-buffered compute, unguarded
// full-tile coalesced 128B-line copy-out.

#define DIM_OUT 64
#define RPB 128          // rows per block == threads
#define HF4 8            // float4 per half-row (32 floats = 128B)
#define PAD 9            // smem row stride in float4

template <bool FULL>
__global__ void __launch_bounds__(RPB) geg_kernel(const float* __restrict__ x,
                                                  float* __restrict__ out,
                                                  int n) {
    __shared__ float4 s[2][RPB * PAD];   // 2 x 18,432 B = 36,864 B

    const int tid = threadIdx.x;
    const size_t row = (size_t)blockIdx.x * RPB + tid;
    const float xv = FULL ? x[row] : ((row < (size_t)n) ? x[row] : 0.0f);

    float4* __restrict__ o4 = reinterpret_cast<float4*>(out);
    const size_t base_f4 = (size_t)blockIdx.x * RPB * (DIM_OUT / 4);
    const size_t total_f4 = ((size_t)n * DIM_OUT) / 4;

    float c[32];
    float prev2 = 1.0f;   // C_0
    float prev  = xv;     // C_1 (alpha = 0.5)
    c[0] = xv;

    // ---- compute C_1..C_32 ----
    // C_i = ((2i-1)*x*C_{i-1} + (1-i)*C_{i-2}) * (1/i)
    #pragma unroll
    for (int i = 2; i <= 32; ++i) {
        const float A = (float)(2 * i - 1);
        const float B = (float)(1 - i);
        const float r = 1.0f / (float)i;
        const float ci = (A * xv * prev + B * prev2) * r;
        c[i - 1] = ci;
        prev2 = prev;
        prev  = ci;
    }

    #pragma unroll
    for (int j = 0; j < HF4; ++j)
        s[0][tid * PAD + j] = make_float4(c[4*j], c[4*j+1], c[4*j+2], c[4*j+3]);
    __syncthreads();

    // ---- copy-out block 0 + compute/stage pass 1 into buffer 1 (no barrier
    //      between them: different smem buffer) ----
    #pragma unroll
    for (int j = 0; j < HF4; ++j) {
        const int f = j * RPB + tid;       // index within 128x8 f4 tile
        const int r = f >> 3;              // row within block
        const int cq = f & 7;              // f4 column within half-row
        const size_t g = base_f4 + (size_t)r * (DIM_OUT / 4) + cq;
        if (FULL) {
            o4[g] = s[0][r * PAD + cq];
        } else if (g < total_f4) {
            o4[g] = s[0][r * PAD + cq];
        }
    }

    // ---- compute C_33..C_64 (overlaps copy-out-0 stores in flight) ----
    #pragma unroll
    for (int i = 33; i <= DIM_OUT; ++i) {
        const float A = (float)(2 * i - 1);
        const float B = (float)(1 - i);
        const float r = 1.0f / (float)i;
        const float ci = (A * xv * prev + B * prev2) * r;
        c[i - 33] = ci;
        prev2 = prev;
        prev  = ci;
    }

    #pragma unroll
    for (int j = 0; j < HF4; ++j)
        s[1][tid * PAD + j] = make_float4(c[4*j], c[4*j+1], c[4*j+2], c[4*j+3]);
    __syncthreads();

    // ---- copy-out block 1 ----
    #pragma unroll
    for (int j = 0; j < HF4; ++j) {
        const int f = j * RPB + tid;
        const int r = f >> 3;
        const int cq = f & 7;
        const size_t g = base_f4 + (size_t)r * (DIM_OUT / 4) + HF4 + cq;
        if (FULL) {
            o4[g] = s[1][r * PAD + cq];
        } else if (g < total_f4) {
            o4[g] = s[1][r * PAD + cq];
        }
    }
    // no trailing barrier: kernel exit synchronizes
}

extern "C" void kernel_launch(void* const* d_in, const int* in_sizes, int n_in,
                              void* d_out, int out_size) {
    const float* x = (const float*)d_in[0];
    float* out = (float*)d_out;
    int n = in_sizes[0];   // 2,000,000 rows = 15625 full tiles of 128
    int blocks = (n + RPB - 1) / RPB;
    if (n % RPB == 0) {
        geg_kernel<true><<<blocks, RPB>>>(x, out, n);
    } else {
        geg_kernel<false><<<blocks, RPB>>>(x, out, n);
    }
}